// round 10
// baseline (speedup 1.0000x reference)
#include <cuda_runtime.h>
#include <cuda_fp16.h>

// ---------------------------------------------------------------------------
// PyramidAttention (UrbanODE core), B=32, C=64, H=W=32, 5 scales, N=3278.
//
//   S[m,q]      = sum_c refm[c,m] * match[c,q]              (K=32 GEMM, fp32)
//   logit[n,p]  = 10*invnorm[n] * sum_d S[n+d, p+d]
//   e           = exp(logit - max), inv[p] = 1/sum e        (fp16 e + fp32 inv)
//   T[p,m]      = sum_d inv[p+d] * e[p+d][m+d]
//   out[c,p]    = x[c,p] + 0.25 * sum_m base[c,m] * T[p,m]  (fp16 HMMA)
//
// R10: S/e/sq live in a ZERO-GUARDED pyramid layout (each level padded by a
// 1-px ring; stride kNSP=3808). Out-of-level taps read 0 => the 9-tap diag
// stencils need NO per-n masks/offsets (R9 profile: softmax 64% ALU-bound).
// invnorm precomputed once per (b,n) inside gemm1's y==0 tile.
// ---------------------------------------------------------------------------

namespace {
constexpr int kB   = 32;
constexpr int kC   = 64;
constexpr int kC2  = 32;
constexpr int kHW  = 1024;
constexpr int kN   = 3278;   // 1024+784+625+484+361
constexpr int kNS  = 3280;   // valid-layout row stride (T)
constexpr int kNSP = 3808;   // padded-layout row stride (S, e, sq); 3802 used
}

// scratch (device globals zero-initialized; guard cells never written)
__device__ float    g_match [(size_t)kB * kC2 * kHW];
__device__ float    g_refm  [(size_t)kB * kC2 * kN];
__device__ __half   g_base16[(size_t)kB * kC  * kN];
__device__ float    g_sqp   [(size_t)kB * kNSP];       // padded sum-of-squares
__device__ float    g_invn  [(size_t)kB * kN];         // 10/patch-norm
__device__ float    g_inv   [(size_t)kB * kHW];        // per-(b,p) 1/sum(e)
__device__ unsigned g_mapn  [kN];                      // np | (ws<<16)
__device__ float    g_S     [(size_t)kB * kHW * kNSP]; // fp32 correlation (padded)
__device__ __half   g_e     [(size_t)kB * kHW * kNSP]; // fp16 exp (padded)
__device__ __half   g_T     [(size_t)kB * kHW * kNS];  // fp16 folded weights (valid)

// pyramid pixel -> (level-local y, x, level width). levels are square.
__device__ __forceinline__ void n_geom(int n, int& ny, int& nx, int& wl)
{
    if (n < 1024)      { int loc = n;        ny = loc >> 5;  nx = loc & 31;     wl = 32; }
    else if (n < 1808) { int loc = n - 1024; ny = loc / 28;  nx = loc - ny*28;  wl = 28; }
    else if (n < 2433) { int loc = n - 1808; ny = loc / 25;  nx = loc - ny*25;  wl = 25; }
    else if (n < 2917) { int loc = n - 2433; ny = loc / 22;  nx = loc - ny*22;  wl = 22; }
    else               { int loc = n - 2917; ny = loc / 19;  nx = loc - ny*19;  wl = 19; }
}

// valid n -> padded index np and padded width ws
__device__ __forceinline__ void n_pad(int n, int& np, int& ws)
{
    int ny, nx, wl;
    n_geom(n, ny, nx, wl);
    int pb;
    if (n < 1024)      pb = 0;
    else if (n < 1808) pb = 1156;
    else if (n < 2433) pb = 2056;
    else if (n < 2917) pb = 2785;
    else               pb = 3361;
    ws = wl + 2;
    np = pb + (ny + 1) * ws + (nx + 1);
}

// ---------------------------------------------------------------------------
// BOTH pyramid conv1x1+prelu projections (x row read once):
// refm (32ch fp32), base (64ch fp16), sq -> padded layout, mapn on b==0.
// ---------------------------------------------------------------------------
__global__ __launch_bounds__(256) void k_conv_pyr(
    const float* __restrict__ x,
    const float* __restrict__ w_match, const float* __restrict__ b_match,
    const float* __restrict__ a_match,
    const float* __restrict__ w_asm, const float* __restrict__ b_asm,
    const float* __restrict__ a_asm)
{
    __shared__ float wsM[kC2 * kC];
    __shared__ float wsA[kC * kC];
    for (int i = threadIdx.x; i < kC2 * kC; i += 256) wsM[i] = w_match[i];
    for (int i = threadIdx.x; i < kC * kC; i += 256)  wsA[i] = w_asm[i];
    __syncthreads();

    int n = blockIdx.x * 256 + threadIdx.x;
    int b = blockIdx.y;
    if (n >= kN) return;

    int ny, nx, wl;
    n_geom(n, ny, nx, wl);
    int sy = (ny * 32) / wl;
    int sx = (nx * 32) / wl;
    const float* xb = x + ((size_t)b * kC) * kHW + sy * 32 + sx;

    float accM[kC2], accA[kC];
#pragma unroll
    for (int co = 0; co < kC2; co++) accM[co] = b_match[co];
#pragma unroll
    for (int co = 0; co < kC; co++)  accA[co] = b_asm[co];
#pragma unroll 2
    for (int c = 0; c < kC; c++) {
        float xv = xb[(size_t)c * kHW];
#pragma unroll
        for (int co = 0; co < kC2; co++) accM[co] = fmaf(wsM[co * kC + c], xv, accM[co]);
#pragma unroll
        for (int co = 0; co < kC; co++)  accA[co] = fmaf(wsA[co * kC + c], xv, accA[co]);
    }
    float alM = a_match[0], alA = a_asm[0];
    float* obM = g_refm + (size_t)b * kC2 * kN + n;
    float sq = 0.f;
#pragma unroll
    for (int co = 0; co < kC2; co++) {
        float v = accM[co];
        v = v >= 0.f ? v : alM * v;
        obM[(size_t)co * kN] = v;
        sq = fmaf(v, v, sq);
    }
    __half* obA = g_base16 + (size_t)b * kC * kN + n;
#pragma unroll
    for (int co = 0; co < kC; co++) {
        float v = accA[co];
        v = v >= 0.f ? v : alA * v;
        obA[(size_t)co * kN] = __float2half(v);
    }

    int np, ws;
    n_pad(n, np, ws);
    g_sqp[(size_t)b * kNSP + np] = sq;
    if (b == 0) g_mapn[n] = (unsigned)np | ((unsigned)ws << 16);
}

// ---------------------------------------------------------------------------
// match_base = prelu(conv1x1(x, w_base)) : [B,32,1024]
// ---------------------------------------------------------------------------
__global__ __launch_bounds__(256) void k_conv_main(
    const float* __restrict__ x, const float* __restrict__ w,
    const float* __restrict__ bias, const float* __restrict__ a)
{
    int t = blockIdx.x * blockDim.x + threadIdx.x;
    if (t >= kB * kC2 * kHW) return;
    int p  = t & (kHW - 1);
    int co = (t >> 10) & 31;
    int b  = t >> 15;
    const float* xb = x + ((size_t)b * kC) * kHW + p;
    const float* wr = w + co * kC;
    float acc = bias[co];
#pragma unroll
    for (int c = 0; c < kC; c++) acc = fmaf(wr[c], xb[(size_t)c * kHW], acc);
    float al = a[0];
    g_match[t] = acc >= 0.f ? acc : al * acc;
}

// ---------------------------------------------------------------------------
// GEMM1 (+ invnorm side-job): S[b][p][np] = sum_c match[b][c][p]*refm[b][c][n]
// 128p x 64n tile, 8x4/thread (R8-measured: 232us, occ 60%). Output scattered
// into the padded layout via g_mapn. blockIdx.y==0 tiles also compute
// invnorm for their 64 n's (guard-free 9-tap on padded sq).
// ---------------------------------------------------------------------------
__global__ __launch_bounds__(256) void k_gemm1()
{
    __shared__ float As[32][132];
    __shared__ float Bs[32][68];
    int b  = blockIdx.z;
    int p0 = blockIdx.y * 128;
    int n0 = blockIdx.x * 64;
    const float* Ab = g_match + (size_t)b * kC2 * kHW;
    const float* Bb = g_refm  + (size_t)b * kC2 * kN;
    int tid = threadIdx.x;
#pragma unroll
    for (int i = tid; i < 32 * 128; i += 256) {
        int k = i >> 7, j = i & 127;
        As[k][j] = Ab[(size_t)k * kHW + p0 + j];
    }
#pragma unroll
    for (int i = tid; i < 32 * 64; i += 256) {
        int k = i >> 6, j = i & 63;
        int n = n0 + j;
        Bs[k][j] = (n < kN) ? Bb[(size_t)k * kN + n] : 0.f;
    }
    __syncthreads();
    int tx = tid & 15, ty = tid >> 4;
    float acc[8][4] = {};
#pragma unroll
    for (int k = 0; k < 32; k++) {
        float av[8], bv[4];
#pragma unroll
        for (int r = 0; r < 8; r++) av[r] = As[k][ty + r * 16];
#pragma unroll
        for (int l = 0; l < 4; l++) bv[l] = Bs[k][tx + l * 16];
#pragma unroll
        for (int r = 0; r < 8; r++)
#pragma unroll
            for (int l = 0; l < 4; l++) acc[r][l] = fmaf(av[r], bv[l], acc[r][l]);
    }
    int npv[4];
#pragma unroll
    for (int l = 0; l < 4; l++) {
        int n = n0 + tx + l * 16;
        npv[l] = (n < kN) ? (int)(g_mapn[n] & 0xFFFFu) : -1;
    }
    float* Sb = g_S + (size_t)b * kHW * kNSP;
#pragma unroll
    for (int r = 0; r < 8; r++) {
        int p = p0 + ty + r * 16;
#pragma unroll
        for (int l = 0; l < 4; l++)
            if (npv[l] >= 0) Sb[(size_t)p * kNSP + npv[l]] = acc[r][l];
    }

    // invnorm side-job (one p-tile per (n-tile, b))
    if (blockIdx.y == 0 && tid < 64) {
        int n = n0 + tid;
        if (n < kN) {
            unsigned u = g_mapn[n];
            int np = (int)(u & 0xFFFFu), ws = (int)(u >> 16);
            const float* sp = g_sqp + (size_t)b * kNSP;
            int cm = np - ws, cp = np + ws;
            float s = sp[cm-1] + sp[cm] + sp[cm+1]
                    + sp[np-1] + sp[np] + sp[np+1]
                    + sp[cp-1] + sp[cp] + sp[cp+1];
            g_invn[(size_t)b * kN + n] = 10.f / fmaxf(sqrtf(s), 1e-4f);
        }
    }
}

// block-uniform p-side validity mask + q-row indices
__device__ __forceinline__ unsigned p_taps(int p, int* qrow)
{
    int py = p >> 5, px = p & 31;
    unsigned pm = 0;
    int i = 0;
#pragma unroll
    for (int dy = -1; dy <= 1; dy++)
#pragma unroll
        for (int dx = -1; dx <= 1; dx++, i++) {
            int qy = py + dy, qx = px + dx;
            qrow[i] = qy * 32 + qx;
            if ((unsigned)qy < 32u && (unsigned)qx < 32u) pm |= 1u << i;
        }
    return pm;
}

// ---------------------------------------------------------------------------
// FUSED softmax: mask-free 9-tap stencil (guards) * invn, row max,
// e=exp(logit-max) -> g_e (padded fp16), inv[p]=1/sum -> g_inv.
// ---------------------------------------------------------------------------
__global__ __launch_bounds__(256) void k_softmax()
{
    __shared__ float row[kNS];
    __shared__ float red[8];
    int p = blockIdx.x, b = blockIdx.y;
    int tid = threadIdx.x;
    int lane = tid & 31, wid = tid >> 5;

    int qrow[9];
    unsigned pm = p_taps(p, qrow);
    const float* S = g_S + (size_t)b * kHW * kNSP;
    const float* Sq[9];
#pragma unroll
    for (int i = 0; i < 9; i++) Sq[i] = S + (size_t)qrow[i] * kNSP;
    const float* invn = g_invn + (size_t)b * kN;

    float mx = -3.4e38f;
    for (int n = tid; n < kN; n += 256) {
        unsigned u = g_mapn[n];
        int np = (int)(u & 0xFFFFu), ws = (int)(u >> 16);
        int cm = np - ws, cp = np + ws;
        float s = 0.f;
        if (pm & 1u)   s += Sq[0][cm - 1];
        if (pm & 2u)   s += Sq[1][cm];
        if (pm & 4u)   s += Sq[2][cm + 1];
        if (pm & 8u)   s += Sq[3][np - 1];
        s += Sq[4][np];                        // center always valid
        if (pm & 32u)  s += Sq[5][np + 1];
        if (pm & 64u)  s += Sq[6][cp - 1];
        if (pm & 128u) s += Sq[7][cp];
        if (pm & 256u) s += Sq[8][cp + 1];
        s *= invn[n];
        row[n] = s;
        mx = fmaxf(mx, s);
    }
#pragma unroll
    for (int o = 16; o; o >>= 1) mx = fmaxf(mx, __shfl_xor_sync(0xffffffffu, mx, o));
    if (lane == 0) red[wid] = mx;
    __syncthreads();
    mx = red[0];
#pragma unroll
    for (int i = 1; i < 8; i++) mx = fmaxf(mx, red[i]);
    __syncthreads();

    float sum = 0.f;
    __half* eo = g_e + ((size_t)b * kHW + p) * kNSP;
    for (int n = tid; n < kN; n += 256) {
        float e = __expf(row[n] - mx);
        sum += e;
        eo[g_mapn[n] & 0xFFFFu] = __float2half(e);
    }
#pragma unroll
    for (int o = 16; o; o >>= 1) sum += __shfl_xor_sync(0xffffffffu, sum, o);
    if (lane == 0) red[wid] = sum;
    __syncthreads();
    if (tid == 0) {
        float s = red[0];
#pragma unroll
        for (int i = 1; i < 8; i++) s += red[i];
        g_inv[(size_t)b * kHW + p] = 1.f / s;
    }
}

// ---------------------------------------------------------------------------
// T[b][p][n] = sum_d inv[p+d] * e[b][p+d][np+d]   (mask-free taps via guards)
// ---------------------------------------------------------------------------
__global__ __launch_bounds__(256) void k_stencilT()
{
    int n = blockIdx.x * 256 + threadIdx.x;
    if (n >= kN) return;
    int p = blockIdx.y, b = blockIdx.z;

    int qrow[9];
    unsigned pm = p_taps(p, qrow);
    const __half* E = g_e + (size_t)b * kHW * kNSP;
    const __half* Eq[9];
    float iv[9];
#pragma unroll
    for (int i = 0; i < 9; i++) {
        Eq[i] = E + (size_t)qrow[i] * kNSP;
        iv[i] = ((pm >> i) & 1u) ? g_inv[(size_t)b * kHW + qrow[i]] : 0.f;
    }

    unsigned u = g_mapn[n];
    int np = (int)(u & 0xFFFFu), ws = (int)(u >> 16);
    int cm = np - ws, cp = np + ws;
    float s = 0.f;
    if (pm & 1u)   s = fmaf(iv[0], __half2float(Eq[0][cm - 1]), s);
    if (pm & 2u)   s = fmaf(iv[1], __half2float(Eq[1][cm]), s);
    if (pm & 4u)   s = fmaf(iv[2], __half2float(Eq[2][cm + 1]), s);
    if (pm & 8u)   s = fmaf(iv[3], __half2float(Eq[3][np - 1]), s);
    s = fmaf(iv[4], __half2float(Eq[4][np]), s);
    if (pm & 32u)  s = fmaf(iv[5], __half2float(Eq[5][np + 1]), s);
    if (pm & 64u)  s = fmaf(iv[6], __half2float(Eq[6][cp - 1]), s);
    if (pm & 128u) s = fmaf(iv[7], __half2float(Eq[7][cp]), s);
    if (pm & 256u) s = fmaf(iv[8], __half2float(Eq[8][cp + 1]), s);
    g_T[((size_t)b * kHW + p) * kNS + n] = __float2half(s);
}

// ---------------------------------------------------------------------------
// GEMM2 on tensor cores: out[b][c][p] = x[b][c][p] + 0.25*sum_m base*T
// 64c x 128p, BK=64; 8 warps 2(c)x4(p); m16n8k16 HMMA fp32 acc (R7-proven).
// ---------------------------------------------------------------------------
__global__ __launch_bounds__(256) void k_gemm2(
    const float* __restrict__ x, float* __restrict__ out)
{
    constexpr int BK = 64;
    constexpr int SA = 72;
    __shared__ __half As[64 * SA];
    __shared__ __half Bs[128 * SA];
    int b  = blockIdx.y;
    int p0 = blockIdx.x * 128;
    const __half* Ab = g_base16 + (size_t)b * kC * kN;
    const __half* Tb = g_T      + (size_t)b * kHW * kNS;
    int tid  = threadIdx.x;
    int lane = tid & 31, warp = tid >> 5;
    int wc = (warp & 1) * 32;
    int wp = (warp >> 1) * 32;
    int gid = lane >> 2, tig = lane & 3;
    float acc[2][4][4] = {};

    for (int k0 = 0; k0 < kN; k0 += BK) {
#pragma unroll
        for (int j = 0; j < 8; j++) {
            int idx = tid + j * 256;
            int c = idx >> 5, kk = (idx & 31) * 2;
            int k = k0 + kk;
            unsigned v = 0;
            if (k < kN) v = *(const unsigned*)(Ab + (size_t)c * kN + k);
            *(unsigned*)(&As[c * SA + kk]) = v;
        }
#pragma unroll
        for (int j = 0; j < 16; j++) {
            int idx = tid + j * 256;
            int pp = idx >> 5, kk = (idx & 31) * 2;
            int k = k0 + kk;
            unsigned v = 0;
            if (k < kN) v = *(const unsigned*)(Tb + (size_t)(p0 + pp) * kNS + k);
            *(unsigned*)(&Bs[pp * SA + kk]) = v;
        }
        __syncthreads();
#pragma unroll
        for (int ks = 0; ks < 4; ks++) {
            int kb = ks * 16;
            unsigned a[2][4], bf[4][2];
#pragma unroll
            for (int mt = 0; mt < 2; mt++) {
                const __half* ap = &As[(wc + mt * 16 + gid) * SA + kb + tig * 2];
                a[mt][0] = *(const unsigned*)(ap);
                a[mt][1] = *(const unsigned*)(ap + 8 * SA);
                a[mt][2] = *(const unsigned*)(ap + 8);
                a[mt][3] = *(const unsigned*)(ap + 8 * SA + 8);
            }
#pragma unroll
            for (int nt = 0; nt < 4; nt++) {
                const __half* bp = &Bs[(wp + nt * 8 + gid) * SA + kb + tig * 2];
                bf[nt][0] = *(const unsigned*)(bp);
                bf[nt][1] = *(const unsigned*)(bp + 8);
            }
#pragma unroll
            for (int mt = 0; mt < 2; mt++)
#pragma unroll
                for (int nt = 0; nt < 4; nt++) {
                    asm volatile(
                        "mma.sync.aligned.m16n8k16.row.col.f32.f16.f16.f32 "
                        "{%0,%1,%2,%3}, {%4,%5,%6,%7}, {%8,%9}, {%0,%1,%2,%3};"
                        : "+f"(acc[mt][nt][0]), "+f"(acc[mt][nt][1]),
                          "+f"(acc[mt][nt][2]), "+f"(acc[mt][nt][3])
                        : "r"(a[mt][0]), "r"(a[mt][1]), "r"(a[mt][2]), "r"(a[mt][3]),
                          "r"(bf[nt][0]), "r"(bf[nt][1]));
                }
        }
        __syncthreads();
    }

    const float* xb = x   + (size_t)b * kC * kHW;
    float*       ob = out + (size_t)b * kC * kHW;
#pragma unroll
    for (int mt = 0; mt < 2; mt++) {
        int c = wc + mt * 16 + gid;
#pragma unroll
        for (int nt = 0; nt < 4; nt++) {
            int pc = p0 + wp + nt * 8 + tig * 2;
            ob[(size_t)c * kHW + pc]           = fmaf(0.25f, acc[mt][nt][0], xb[(size_t)c * kHW + pc]);
            ob[(size_t)c * kHW + pc + 1]       = fmaf(0.25f, acc[mt][nt][1], xb[(size_t)c * kHW + pc + 1]);
            ob[(size_t)(c + 8) * kHW + pc]     = fmaf(0.25f, acc[mt][nt][2], xb[(size_t)(c + 8) * kHW + pc]);
            ob[(size_t)(c + 8) * kHW + pc + 1] = fmaf(0.25f, acc[mt][nt][3], xb[(size_t)(c + 8) * kHW + pc + 1]);
        }
    }
}

// ---------------------------------------------------------------------------
extern "C" void kernel_launch(void* const* d_in, const int* in_sizes, int n_in,
                              void* d_out, int out_size)
{
    (void)in_sizes; (void)n_in; (void)out_size;
    const float* x       = (const float*)d_in[0];
    const float* w_base  = (const float*)d_in[1];
    const float* b_base  = (const float*)d_in[2];
    const float* a_base  = (const float*)d_in[3];
    const float* w_match = (const float*)d_in[4];
    const float* b_match = (const float*)d_in[5];
    const float* a_match = (const float*)d_in[6];
    const float* w_asm   = (const float*)d_in[7];
    const float* b_asm   = (const float*)d_in[8];
    const float* a_asm   = (const float*)d_in[9];
    float* out = (float*)d_out;

    {
        dim3 g((kN + 255) / 256, kB);
        k_conv_pyr<<<g, 256>>>(x, w_match, b_match, a_match, w_asm, b_asm, a_asm); // 1
    }
    k_conv_main<<<(kB * kC2 * kHW + 255) / 256, 256>>>(x, w_base, b_base, a_base); // 2
    {
        dim3 g((kN + 63) / 64, kHW / 128, kB);
        k_gemm1<<<g, 256>>>();                                                     // 3 (+invn)
    }
    {
        dim3 g(kHW, kB);
        k_softmax<<<g, 256>>>();                                                   // 4 (profiled)
    }
    {
        dim3 g((kN + 255) / 256, kHW, kB);
        k_stencilT<<<g, 256>>>();                                                  // 5
    }
    {
        dim3 g(kHW / 128, kB);
        k_gemm2<<<g, 256>>>(x, out);                                               // 6
    }
}

// round 11
// speedup vs baseline: 1.5368x; 1.5368x over previous
#include <cuda_runtime.h>
#include <cuda_fp16.h>

// ---------------------------------------------------------------------------
// PyramidAttention (UrbanODE core), B=32, C=64, H=W=32, 5 scales, N=3278.
//
//   S[m,q]      = sum_c refm[c,m] * match[c,q]              (K=32 GEMM, fp32)
//   logit[n,p]  = 10*invnorm[n] * sum_d S[n+d, p+d]
//   e           = exp(logit - max), inv[p] = 1/sum e        (fp16 e + fp32 inv)
//   T[p,m]      = sum_d inv[p+d] * e[p+d][m+d]
//   out[c,p]    = x[c,p] + 0.25 * sum_m base[c,m] * T[p,m]  (fp16 HMMA)
//
// R11: stencilT restructured block-per-(p,b) with n-loop (R10 paid ~60 setup
// instrs incl. 9 g_inv LDGs per SINGLE n => ~950us). Branch-free 9-tap via
// zero-row pointers for invalid p-taps. Convs merged (stencilT -> slot 4).
// ---------------------------------------------------------------------------

namespace {
constexpr int kB   = 32;
constexpr int kC   = 64;
constexpr int kC2  = 32;
constexpr int kHW  = 1024;
constexpr int kN   = 3278;   // 1024+784+625+484+361
constexpr int kNS  = 3280;   // valid-layout row stride (T)
constexpr int kNSP = 3808;   // padded-layout row stride (S, e, sq)
}

// scratch (device globals zero-initialized; guard cells / zero rows never written)
__device__ float    g_match [(size_t)kB * kC2 * kHW];
__device__ float    g_refm  [(size_t)kB * kC2 * kN];
__device__ __half   g_base16[(size_t)kB * kC  * kN];
__device__ float    g_sqp   [(size_t)kB * kNSP];
__device__ float    g_invn  [(size_t)kB * kN];
__device__ float    g_inv   [(size_t)kB * kHW];
__device__ unsigned g_mapn  [kN];                      // np | (ws<<16)
__device__ float    g_zeroF [kNSP + 64];               // never written
__device__ __half   g_zeroH [kNSP + 64];               // never written
__device__ float    g_S     [(size_t)kB * kHW * kNSP];
__device__ __half   g_e     [(size_t)kB * kHW * kNSP];
__device__ __half   g_T     [(size_t)kB * kHW * kNS];

// pyramid pixel -> (level-local y, x, level width)
__device__ __forceinline__ void n_geom(int n, int& ny, int& nx, int& wl)
{
    if (n < 1024)      { int loc = n;        ny = loc >> 5;  nx = loc & 31;     wl = 32; }
    else if (n < 1808) { int loc = n - 1024; ny = loc / 28;  nx = loc - ny*28;  wl = 28; }
    else if (n < 2433) { int loc = n - 1808; ny = loc / 25;  nx = loc - ny*25;  wl = 25; }
    else if (n < 2917) { int loc = n - 2433; ny = loc / 22;  nx = loc - ny*22;  wl = 22; }
    else               { int loc = n - 2917; ny = loc / 19;  nx = loc - ny*19;  wl = 19; }
}

// valid n -> padded index np and padded width ws
__device__ __forceinline__ void n_pad(int n, int& np, int& ws)
{
    int ny, nx, wl;
    n_geom(n, ny, nx, wl);
    int pb;
    if (n < 1024)      pb = 0;
    else if (n < 1808) pb = 1156;
    else if (n < 2433) pb = 2056;
    else if (n < 2917) pb = 2785;
    else               pb = 3361;
    ws = wl + 2;
    np = pb + (ny + 1) * ws + (nx + 1);
}

// ---------------------------------------------------------------------------
// ALL projections in one kernel. blocks x<13: pyramid (refm fp32 + sq + base
// fp16 + mapn); x>=13: main (match fp32, thread = p, 32 channels).
// ---------------------------------------------------------------------------
__global__ __launch_bounds__(256) void k_conv_all(
    const float* __restrict__ x,
    const float* __restrict__ w_base,  const float* __restrict__ b_base,
    const float* __restrict__ a_base,
    const float* __restrict__ w_match, const float* __restrict__ b_match,
    const float* __restrict__ a_match,
    const float* __restrict__ w_asm,   const float* __restrict__ b_asm,
    const float* __restrict__ a_asm)
{
    __shared__ float ws[kC2 * kC + kC * kC];   // pyr: M|A ; main: base
    int b = blockIdx.y;
    int tid = threadIdx.x;

    if (blockIdx.x < 13) {
        // ---- pyramid branch ----
        for (int i = tid; i < kC2 * kC; i += 256) ws[i] = w_match[i];
        for (int i = tid; i < kC * kC; i += 256)  ws[kC2 * kC + i] = w_asm[i];
        __syncthreads();
        int n = blockIdx.x * 256 + tid;
        if (n >= kN) return;

        int ny, nx, wl;
        n_geom(n, ny, nx, wl);
        int sy = (ny * 32) / wl;
        int sx = (nx * 32) / wl;
        const float* xb = x + ((size_t)b * kC) * kHW + sy * 32 + sx;

        float accM[kC2], accA[kC];
#pragma unroll
        for (int co = 0; co < kC2; co++) accM[co] = b_match[co];
#pragma unroll
        for (int co = 0; co < kC; co++)  accA[co] = b_asm[co];
#pragma unroll 2
        for (int c = 0; c < kC; c++) {
            float xv = xb[(size_t)c * kHW];
#pragma unroll
            for (int co = 0; co < kC2; co++) accM[co] = fmaf(ws[co * kC + c], xv, accM[co]);
#pragma unroll
            for (int co = 0; co < kC; co++)  accA[co] = fmaf(ws[kC2 * kC + co * kC + c], xv, accA[co]);
        }
        float alM = a_match[0], alA = a_asm[0];
        float* obM = g_refm + (size_t)b * kC2 * kN + n;
        float sq = 0.f;
#pragma unroll
        for (int co = 0; co < kC2; co++) {
            float v = accM[co];
            v = v >= 0.f ? v : alM * v;
            obM[(size_t)co * kN] = v;
            sq = fmaf(v, v, sq);
        }
        __half* obA = g_base16 + (size_t)b * kC * kN + n;
#pragma unroll
        for (int co = 0; co < kC; co++) {
            float v = accA[co];
            v = v >= 0.f ? v : alA * v;
            obA[(size_t)co * kN] = __float2half(v);
        }
        int np, wss;
        n_pad(n, np, wss);
        g_sqp[(size_t)b * kNSP + np] = sq;
        if (b == 0) g_mapn[n] = (unsigned)np | ((unsigned)wss << 16);
    } else {
        // ---- main branch: match = prelu(conv1x1(x, w_base)) ----
        for (int i = tid; i < kC2 * kC; i += 256) ws[i] = w_base[i];
        __syncthreads();
        int p = (blockIdx.x - 13) * 256 + tid;
        const float* xb = x + ((size_t)b * kC) * kHW + p;
        float acc[kC2];
#pragma unroll
        for (int co = 0; co < kC2; co++) acc[co] = b_base[co];
#pragma unroll 2
        for (int c = 0; c < kC; c++) {
            float xv = xb[(size_t)c * kHW];
#pragma unroll
            for (int co = 0; co < kC2; co++) acc[co] = fmaf(ws[co * kC + c], xv, acc[co]);
        }
        float al = a_base[0];
        float* ob = g_match + (size_t)b * kC2 * kHW + p;
#pragma unroll
        for (int co = 0; co < kC2; co++) {
            float v = acc[co];
            ob[(size_t)co * kHW] = v >= 0.f ? v : al * v;
        }
    }
}

// ---------------------------------------------------------------------------
// GEMM1 (+ invnorm side-job): S[b][p][np] = sum_c match[b][c][p]*refm[b][c][n]
// 128p x 64n tile, 8x4/thread; scatter via g_mapn into padded layout.
// ---------------------------------------------------------------------------
__global__ __launch_bounds__(256) void k_gemm1()
{
    __shared__ float As[32][132];
    __shared__ float Bs[32][68];
    int b  = blockIdx.z;
    int p0 = blockIdx.y * 128;
    int n0 = blockIdx.x * 64;
    const float* Ab = g_match + (size_t)b * kC2 * kHW;
    const float* Bb = g_refm  + (size_t)b * kC2 * kN;
    int tid = threadIdx.x;
#pragma unroll
    for (int i = tid; i < 32 * 128; i += 256) {
        int k = i >> 7, j = i & 127;
        As[k][j] = Ab[(size_t)k * kHW + p0 + j];
    }
#pragma unroll
    for (int i = tid; i < 32 * 64; i += 256) {
        int k = i >> 6, j = i & 63;
        int n = n0 + j;
        Bs[k][j] = (n < kN) ? Bb[(size_t)k * kN + n] : 0.f;
    }
    __syncthreads();
    int tx = tid & 15, ty = tid >> 4;
    float acc[8][4] = {};
#pragma unroll
    for (int k = 0; k < 32; k++) {
        float av[8], bv[4];
#pragma unroll
        for (int r = 0; r < 8; r++) av[r] = As[k][ty + r * 16];
#pragma unroll
        for (int l = 0; l < 4; l++) bv[l] = Bs[k][tx + l * 16];
#pragma unroll
        for (int r = 0; r < 8; r++)
#pragma unroll
            for (int l = 0; l < 4; l++) acc[r][l] = fmaf(av[r], bv[l], acc[r][l]);
    }
    int npv[4];
#pragma unroll
    for (int l = 0; l < 4; l++) {
        int n = n0 + tx + l * 16;
        npv[l] = (n < kN) ? (int)(g_mapn[n] & 0xFFFFu) : -1;
    }
    float* Sb = g_S + (size_t)b * kHW * kNSP;
#pragma unroll
    for (int r = 0; r < 8; r++) {
        int p = p0 + ty + r * 16;
#pragma unroll
        for (int l = 0; l < 4; l++)
            if (npv[l] >= 0) Sb[(size_t)p * kNSP + npv[l]] = acc[r][l];
    }

    if (blockIdx.y == 0 && tid < 64) {
        int n = n0 + tid;
        if (n < kN) {
            unsigned u = g_mapn[n];
            int np = (int)(u & 0xFFFFu), wss = (int)(u >> 16);
            const float* sp = g_sqp + (size_t)b * kNSP;
            int cm = np - wss, cp = np + wss;
            float s = sp[cm-1] + sp[cm] + sp[cm+1]
                    + sp[np-1] + sp[np] + sp[np+1]
                    + sp[cp-1] + sp[cp] + sp[cp+1];
            g_invn[(size_t)b * kN + n] = 10.f / fmaxf(sqrtf(s), 1e-4f);
        }
    }
}

// block-uniform p-side validity + q-row indices
__device__ __forceinline__ unsigned p_taps(int p, int* qrow)
{
    int py = p >> 5, px = p & 31;
    unsigned pm = 0;
    int i = 0;
#pragma unroll
    for (int dy = -1; dy <= 1; dy++)
#pragma unroll
        for (int dx = -1; dx <= 1; dx++, i++) {
            int qy = py + dy, qx = px + dx;
            qrow[i] = qy * 32 + qx;
            if ((unsigned)qy < 32u && (unsigned)qx < 32u) pm |= 1u << i;
        }
    return pm;
}

// ---------------------------------------------------------------------------
// FUSED softmax: branch-free 9-tap (invalid p-taps -> zero row) * invn,
// row max, e=exp(logit-max) -> g_e (padded fp16), inv[p]=1/sum -> g_inv.
// ---------------------------------------------------------------------------
__global__ __launch_bounds__(256) void k_softmax()
{
    __shared__ float row[kNS];
    __shared__ unsigned short nps[kNS];
    __shared__ float red[8];
    int p = blockIdx.x, b = blockIdx.y;
    int tid = threadIdx.x;
    int lane = tid & 31, wid = tid >> 5;

    int qrow[9];
    unsigned pm = p_taps(p, qrow);
    const float* S = g_S + (size_t)b * kHW * kNSP;
    const float* Sq[9];
#pragma unroll
    for (int i = 0; i < 9; i++)
        Sq[i] = ((pm >> i) & 1u) ? (S + (size_t)qrow[i] * kNSP) : g_zeroF;
    const float* invn = g_invn + (size_t)b * kN;

    float mx = -3.4e38f;
    for (int n = tid; n < kN; n += 256) {
        unsigned u = g_mapn[n];
        int np = (int)(u & 0xFFFFu), wss = (int)(u >> 16);
        nps[n] = (unsigned short)np;
        int cm = np - wss, cp = np + wss;
        float s = Sq[0][cm - 1] + Sq[1][cm] + Sq[2][cm + 1]
                + Sq[3][np - 1] + Sq[4][np] + Sq[5][np + 1]
                + Sq[6][cp - 1] + Sq[7][cp] + Sq[8][cp + 1];
        s *= invn[n];
        row[n] = s;
        mx = fmaxf(mx, s);
    }
#pragma unroll
    for (int o = 16; o; o >>= 1) mx = fmaxf(mx, __shfl_xor_sync(0xffffffffu, mx, o));
    if (lane == 0) red[wid] = mx;
    __syncthreads();
    mx = red[0];
#pragma unroll
    for (int i = 1; i < 8; i++) mx = fmaxf(mx, red[i]);
    __syncthreads();

    float sum = 0.f;
    __half* eo = g_e + ((size_t)b * kHW + p) * kNSP;
    for (int n = tid; n < kN; n += 256) {
        float e = __expf(row[n] - mx);
        sum += e;
        eo[nps[n]] = __float2half(e);
    }
#pragma unroll
    for (int o = 16; o; o >>= 1) sum += __shfl_xor_sync(0xffffffffu, sum, o);
    if (lane == 0) red[wid] = sum;
    __syncthreads();
    if (tid == 0) {
        float s = red[0];
#pragma unroll
        for (int i = 1; i < 8; i++) s += red[i];
        g_inv[(size_t)b * kHW + p] = 1.f / s;
    }
}

// ---------------------------------------------------------------------------
// T[b][p][n] = sum_d inv[p+d] * e[b][p+d][np+d]
// Block per (p,b); setup hoisted; branch-free 9 fmaf inner loop (iv=0 and
// zero-row pointer for invalid p-taps).
// ---------------------------------------------------------------------------
__global__ __launch_bounds__(256) void k_stencilT()
{
    int p = blockIdx.x, b = blockIdx.y;
    int tid = threadIdx.x;

    int qrow[9];
    unsigned pm = p_taps(p, qrow);
    const __half* E = g_e + (size_t)b * kHW * kNSP;
    const __half* Eq[9];
    float iv[9];
#pragma unroll
    for (int i = 0; i < 9; i++) {
        bool v = (pm >> i) & 1u;
        Eq[i] = v ? (E + (size_t)qrow[i] * kNSP) : g_zeroH;
        iv[i] = v ? g_inv[(size_t)b * kHW + qrow[i]] : 0.f;
    }
    __half* To = g_T + ((size_t)b * kHW + p) * kNS;

    for (int n = tid; n < kN; n += 256) {
        unsigned u = g_mapn[n];
        int np = (int)(u & 0xFFFFu), wss = (int)(u >> 16);
        int cm = np - wss, cp = np + wss;
        float s;
        s = iv[0] * __half2float(Eq[0][cm - 1]);
        s = fmaf(iv[1], __half2float(Eq[1][cm]),     s);
        s = fmaf(iv[2], __half2float(Eq[2][cm + 1]), s);
        s = fmaf(iv[3], __half2float(Eq[3][np - 1]), s);
        s = fmaf(iv[4], __half2float(Eq[4][np]),     s);
        s = fmaf(iv[5], __half2float(Eq[5][np + 1]), s);
        s = fmaf(iv[6], __half2float(Eq[6][cp - 1]), s);
        s = fmaf(iv[7], __half2float(Eq[7][cp]),     s);
        s = fmaf(iv[8], __half2float(Eq[8][cp + 1]), s);
        To[n] = __float2half(s);
    }
}

// ---------------------------------------------------------------------------
// GEMM2 on tensor cores: out[b][c][p] = x[b][c][p] + 0.25*sum_m base*T
// 64c x 128p, BK=64; 8 warps 2(c)x4(p); m16n8k16 HMMA fp32 acc (R7-proven).
// ---------------------------------------------------------------------------
__global__ __launch_bounds__(256) void k_gemm2(
    const float* __restrict__ x, float* __restrict__ out)
{
    constexpr int BK = 64;
    constexpr int SA = 72;
    __shared__ __half As[64 * SA];
    __shared__ __half Bs[128 * SA];
    int b  = blockIdx.y;
    int p0 = blockIdx.x * 128;
    const __half* Ab = g_base16 + (size_t)b * kC * kN;
    const __half* Tb = g_T      + (size_t)b * kHW * kNS;
    int tid  = threadIdx.x;
    int lane = tid & 31, warp = tid >> 5;
    int wc = (warp & 1) * 32;
    int wp = (warp >> 1) * 32;
    int gid = lane >> 2, tig = lane & 3;
    float acc[2][4][4] = {};

    for (int k0 = 0; k0 < kN; k0 += BK) {
#pragma unroll
        for (int j = 0; j < 8; j++) {
            int idx = tid + j * 256;
            int c = idx >> 5, kk = (idx & 31) * 2;
            int k = k0 + kk;
            unsigned v = 0;
            if (k < kN) v = *(const unsigned*)(Ab + (size_t)c * kN + k);
            *(unsigned*)(&As[c * SA + kk]) = v;
        }
#pragma unroll
        for (int j = 0; j < 16; j++) {
            int idx = tid + j * 256;
            int pp = idx >> 5, kk = (idx & 31) * 2;
            int k = k0 + kk;
            unsigned v = 0;
            if (k < kN) v = *(const unsigned*)(Tb + (size_t)(p0 + pp) * kNS + k);
            *(unsigned*)(&Bs[pp * SA + kk]) = v;
        }
        __syncthreads();
#pragma unroll
        for (int ks = 0; ks < 4; ks++) {
            int kb = ks * 16;
            unsigned a[2][4], bf[4][2];
#pragma unroll
            for (int mt = 0; mt < 2; mt++) {
                const __half* ap = &As[(wc + mt * 16 + gid) * SA + kb + tig * 2];
                a[mt][0] = *(const unsigned*)(ap);
                a[mt][1] = *(const unsigned*)(ap + 8 * SA);
                a[mt][2] = *(const unsigned*)(ap + 8);
                a[mt][3] = *(const unsigned*)(ap + 8 * SA + 8);
            }
#pragma unroll
            for (int nt = 0; nt < 4; nt++) {
                const __half* bp = &Bs[(wp + nt * 8 + gid) * SA + kb + tig * 2];
                bf[nt][0] = *(const unsigned*)(bp);
                bf[nt][1] = *(const unsigned*)(bp + 8);
            }
#pragma unroll
            for (int mt = 0; mt < 2; mt++)
#pragma unroll
                for (int nt = 0; nt < 4; nt++) {
                    asm volatile(
                        "mma.sync.aligned.m16n8k16.row.col.f32.f16.f16.f32 "
                        "{%0,%1,%2,%3}, {%4,%5,%6,%7}, {%8,%9}, {%0,%1,%2,%3};"
                        : "+f"(acc[mt][nt][0]), "+f"(acc[mt][nt][1]),
                          "+f"(acc[mt][nt][2]), "+f"(acc[mt][nt][3])
                        : "r"(a[mt][0]), "r"(a[mt][1]), "r"(a[mt][2]), "r"(a[mt][3]),
                          "r"(bf[nt][0]), "r"(bf[nt][1]));
                }
        }
        __syncthreads();
    }

    const float* xb = x   + (size_t)b * kC * kHW;
    float*       ob = out + (size_t)b * kC * kHW;
#pragma unroll
    for (int mt = 0; mt < 2; mt++) {
        int c = wc + mt * 16 + gid;
#pragma unroll
        for (int nt = 0; nt < 4; nt++) {
            int pc = p0 + wp + nt * 8 + tig * 2;
            ob[(size_t)c * kHW + pc]           = fmaf(0.25f, acc[mt][nt][0], xb[(size_t)c * kHW + pc]);
            ob[(size_t)c * kHW + pc + 1]       = fmaf(0.25f, acc[mt][nt][1], xb[(size_t)c * kHW + pc + 1]);
            ob[(size_t)(c + 8) * kHW + pc]     = fmaf(0.25f, acc[mt][nt][2], xb[(size_t)(c + 8) * kHW + pc]);
            ob[(size_t)(c + 8) * kHW + pc + 1] = fmaf(0.25f, acc[mt][nt][3], xb[(size_t)(c + 8) * kHW + pc + 1]);
        }
    }
}

// ---------------------------------------------------------------------------
extern "C" void kernel_launch(void* const* d_in, const int* in_sizes, int n_in,
                              void* d_out, int out_size)
{
    (void)in_sizes; (void)n_in; (void)out_size;
    const float* x       = (const float*)d_in[0];
    const float* w_base  = (const float*)d_in[1];
    const float* b_base  = (const float*)d_in[2];
    const float* a_base  = (const float*)d_in[3];
    const float* w_match = (const float*)d_in[4];
    const float* b_match = (const float*)d_in[5];
    const float* a_match = (const float*)d_in[6];
    const float* w_asm   = (const float*)d_in[7];
    const float* b_asm   = (const float*)d_in[8];
    const float* a_asm   = (const float*)d_in[9];
    float* out = (float*)d_out;

    {
        dim3 g(17, kB);   // 13 pyramid blocks + 4 main blocks per batch
        k_conv_all<<<g, 256>>>(x, w_base, b_base, a_base,
                               w_match, b_match, a_match,
                               w_asm, b_asm, a_asm);                 // 1
    }
    {
        dim3 g((kN + 63) / 64, kHW / 128, kB);
        k_gemm1<<<g, 256>>>();                                       // 2 (+invn)
    }
    {
        dim3 g(kHW, kB);
        k_softmax<<<g, 256>>>();                                     // 3
        k_stencilT<<<g, 256>>>();                                    // 4 (profiled)
    }
    {
        dim3 g(kHW / 128, kB);
        k_gemm2<<<g, 256>>>(x, out);                                 // 5
    }
}